// round 14
// baseline (speedup 1.0000x reference)
#include <cuda_runtime.h>
#include <cuda_bf16.h>
#include <cstdint>
#include <math.h>

#define NQ 8192
#define NK 8192
#define DIM 512
#define CSCALE 0.01f
// exp(-0.5*(qd+kd)+55) = 2^(-0.5*log2e*(qd+kd) + 55*log2e)
#define NEG_HALF_LOG2E (-0.72134752044448170f)
#define SHIFT_LOG2E    (79.34822724889299f)

// ---------------------------------------------------------------------------
// Scratch (static device arrays; no runtime allocation)
// ---------------------------------------------------------------------------
__device__ __nv_bfloat16 g_qh[NQ * DIM];
__device__ __nv_bfloat16 g_ql[NQ * DIM];
__device__ __nv_bfloat16 g_kh[NK * DIM];
__device__ __nv_bfloat16 g_kl[NK * DIM];
__device__ float g_qq[NQ];
__device__ float g_kk[NK];
__device__ float g_rsum[NQ];

// ---------------------------------------------------------------------------
// helpers
// ---------------------------------------------------------------------------
__device__ __forceinline__ uint32_t smem_u32(const void* p) {
    uint32_t a;
    asm("{ .reg .u64 t; cvta.to.shared.u64 t, %1; cvt.u32.u64 %0, t; }" : "=r"(a) : "l"(p));
    return a;
}

// Full SW128 swizzle for 128-byte rows: bits[6:4] ^= bits[9:7]
#define SWZ128(off) ((off) ^ (((off) >> 3) & 0x70))

__device__ __forceinline__ void cp_async16(uint32_t dst, const void* src) {
    asm volatile("cp.async.cg.shared.global [%0], [%1], 16;" :: "r"(dst), "l"(src));
}

__device__ __forceinline__ void ldsm_x4(uint32_t& r0, uint32_t& r1, uint32_t& r2, uint32_t& r3,
                                        uint32_t addr) {
    asm volatile("ldmatrix.sync.aligned.m8n8.x4.shared.b16 {%0,%1,%2,%3}, [%4];"
                 : "=r"(r0), "=r"(r1), "=r"(r2), "=r"(r3) : "r"(addr));
}

__device__ __forceinline__ void mma16816(float* c, uint32_t a0, uint32_t a1, uint32_t a2,
                                         uint32_t a3, uint32_t b0, uint32_t b1) {
    asm volatile(
        "mma.sync.aligned.m16n8k16.row.col.f32.bf16.bf16.f32 "
        "{%0,%1,%2,%3}, {%4,%5,%6,%7}, {%8,%9}, {%0,%1,%2,%3};"
        : "+f"(c[0]), "+f"(c[1]), "+f"(c[2]), "+f"(c[3])
        : "r"(a0), "r"(a1), "r"(a2), "r"(a3), "r"(b0), "r"(b1));
}

__device__ __forceinline__ float fsqrt_approx(float x) {
    float r; asm("sqrt.approx.f32 %0, %1;" : "=f"(r) : "f"(x)); return r;
}
__device__ __forceinline__ float fexp2_approx(float x) {
    float r; asm("ex2.approx.f32 %0, %1;" : "=f"(r) : "f"(x)); return r;
}

// exp(score + 55) with fixed shift (softmax-invariant; scores always << 0)
__device__ __forceinline__ float score_exp(float qk, float qq, float kk) {
    float norm2 = fmaxf(qq + kk - 2.0f * qk, 0.0f);
    float qdot  = qq - qk;
    float kdot  = qk - kk;
    float qd = fsqrt_approx(fmaf(CSCALE * qdot, qdot, norm2));
    float kd = fsqrt_approx(fmaf(CSCALE * kdot, kdot, norm2));
    return fexp2_approx(fmaf(NEG_HALF_LOG2E, qd + kd, SHIFT_LOG2E));
}

// ---------------------------------------------------------------------------
// Kernel 1: per-row sumsq + bf16 hi/lo split. One warp per row. Zeroes g_rsum.
// ---------------------------------------------------------------------------
__global__ void __launch_bounds__(256)
prep_kernel(const float* __restrict__ Q, const float* __restrict__ Kp) {
    int gw   = (blockIdx.x * blockDim.x + threadIdx.x) >> 5;
    int lane = threadIdx.x & 31;
    bool isQ = gw < NQ;
    int row  = isQ ? gw : gw - NQ;
    const float4* src = reinterpret_cast<const float4*>((isQ ? Q : Kp) + (size_t)row * DIM);
    __nv_bfloat16* hi = isQ ? g_qh : g_kh;
    __nv_bfloat16* lo = isQ ? g_ql : g_kl;

    float s = 0.0f;
#pragma unroll
    for (int i = 0; i < DIM / 128; i++) {
        float4 v = src[i * 32 + lane];
        s = fmaf(v.x, v.x, s); s = fmaf(v.y, v.y, s);
        s = fmaf(v.z, v.z, s); s = fmaf(v.w, v.w, s);

        __nv_bfloat16 h0 = __float2bfloat16(v.x);
        __nv_bfloat16 h1 = __float2bfloat16(v.y);
        __nv_bfloat16 h2 = __float2bfloat16(v.z);
        __nv_bfloat16 h3 = __float2bfloat16(v.w);
        __nv_bfloat16 l0 = __float2bfloat16(v.x - __bfloat162float(h0));
        __nv_bfloat16 l1 = __float2bfloat16(v.y - __bfloat162float(h1));
        __nv_bfloat16 l2 = __float2bfloat16(v.z - __bfloat162float(h2));
        __nv_bfloat16 l3 = __float2bfloat16(v.w - __bfloat162float(h3));

        int col = (i * 32 + lane) * 4;
        __nv_bfloat162 h01 = __nv_bfloat162(h0, h1);
        __nv_bfloat162 h23 = __nv_bfloat162(h2, h3);
        __nv_bfloat162 l01 = __nv_bfloat162(l0, l1);
        __nv_bfloat162 l23 = __nv_bfloat162(l2, l3);
        uint2 hu = make_uint2(*reinterpret_cast<uint32_t*>(&h01), *reinterpret_cast<uint32_t*>(&h23));
        uint2 lu = make_uint2(*reinterpret_cast<uint32_t*>(&l01), *reinterpret_cast<uint32_t*>(&l23));
        *reinterpret_cast<uint2*>(hi + (size_t)row * DIM + col) = hu;
        *reinterpret_cast<uint2*>(lo + (size_t)row * DIM + col) = lu;
    }
#pragma unroll
    for (int off = 16; off; off >>= 1) s += __shfl_xor_sync(0xFFFFFFFFu, s, off);
    if (lane == 0) {
        if (isQ) { g_qq[row] = s; g_rsum[row] = 0.0f; }
        else     { g_kk[row] = s; }
    }
}

// ---------------------------------------------------------------------------
// Kernel 2: mma.sync bf16 split GEMM (K_eff=1536) + fused score/exp epilogue.
// OCCUPANCY-FIRST shape: CTA tile 128x64, 8 warps (2x4), warptile 64x16,
// ~75 regs/thread + 50KB smem -> 3 CTAs/SM (24 warps, 6/SMSP) to cover the
// exposed ldsm/HMMA latency that held tensor busy at 48% with 16 warps.
// 2-stage pipeline (depth-1 prefetch), K-chunk 64, SW128 rows.
// ---------------------------------------------------------------------------
#define NCHUNK 24
#define CK 64
#define ABUF 16384          // 128 rows x 128B
#define BBUF 8192           // 64 rows x 128B
#define STAGE_B (ABUF + BBUF)
#define DYN_SMEM (2 * STAGE_B + 1024)

__global__ void __launch_bounds__(256, 3)
gemm_score_kernel(float* __restrict__ out) {
    extern __shared__ __align__(1024) uint8_t dyn_smem[];
    uint32_t sbase0 = smem_u32(dyn_smem);
    uint32_t sbase  = (sbase0 + 1023u) & ~1023u;

    const int tid  = threadIdx.x;
    const int wid  = tid >> 5;
    const int lane = tid & 31;
    const int bm = blockIdx.y;
    const int bn = blockIdx.x;
    const int warp_m = wid & 1;     // 0..1 -> 64-row half
    const int warp_n = wid >> 1;    // 0..3 -> 16-col slice

    // per-lane swizzled ldsm base offsets; addr(ks) = base ^ (ks << 5)
    uint32_t baseA[4], baseB;
#pragma unroll
    for (int mt = 0; mt < 4; mt++) {
        int m  = warp_m * 64 + mt * 16 + (lane & 15);
        int lo = (lane >> 4) * 16;
        baseA[mt] = (uint32_t)(m * 128 + lo) ^ (uint32_t)((m & 7) * 16);
    }
    {
        int n  = warp_n * 16 + (lane & 7) + ((lane >> 4) & 1) * 8;
        int lo = ((lane >> 3) & 1) * 16;
        baseB = (uint32_t)(n * 128 + lo) ^ (uint32_t)((n & 7) * 16);
    }

    // loaders: A 128 rows x 8 segs (2 thr/row x 4 segs); B 64 rows x 8 segs
    const int larow = tid >> 1;           // 0..127
    const int laseg = (tid & 1) * 4;
    const int lbrow = tid >> 2;           // 0..63
    const int lbseg = (tid & 3) * 2;

    auto issue_chunk = [&](int c, int buf) {
        const __nv_bfloat16 *as, *bs;
        if (c < 8)       { as = g_qh; bs = g_kh; }
        else if (c < 16) { as = g_qh; bs = g_kl; }
        else             { as = g_ql; bs = g_kh; }
        int kc = (c & 7) * CK;
        uint32_t stg = sbase + buf * STAGE_B;
        const __nv_bfloat16* ag = as + (size_t)(bm * 128 + larow) * DIM + kc;
#pragma unroll
        for (int i = 0; i < 4; i++) {
            int seg = laseg + i;
            cp_async16(stg + SWZ128(larow * 128 + seg * 16), ag + seg * 8);
        }
        const __nv_bfloat16* bg = bs + (size_t)(bn * 64 + lbrow) * DIM + kc;
#pragma unroll
        for (int i = 0; i < 2; i++) {
            int seg = lbseg + i;
            cp_async16(stg + ABUF + SWZ128(lbrow * 128 + seg * 16), bg + seg * 8);
        }
        asm volatile("cp.async.commit_group;" ::: "memory");
    };

    float acc[4][2][4];
#pragma unroll
    for (int mt = 0; mt < 4; mt++)
#pragma unroll
        for (int nt = 0; nt < 2; nt++)
#pragma unroll
            for (int i = 0; i < 4; i++) acc[mt][nt][i] = 0.0f;

    issue_chunk(0, 0);

    for (int c = 0; c < NCHUNK; c++) {
        asm volatile("cp.async.wait_group 0;" ::: "memory");
        __syncthreads();
        // depth-1 prefetch: other buffer's readers finished before the barrier
        if (c + 1 < NCHUNK) issue_chunk(c + 1, (c + 1) & 1);

        uint32_t stg = sbase + (c & 1) * STAGE_B;
        uint32_t sa  = stg;
        uint32_t sbb = stg + ABUF;
#pragma unroll
        for (int ks = 0; ks < 4; ks++) {
            uint32_t kx = (uint32_t)(ks << 5);
            uint32_t b[4];
            ldsm_x4(b[0], b[1], b[2], b[3], sbb + (baseB ^ kx));
            uint32_t a[4][4];
#pragma unroll
            for (int mt = 0; mt < 4; mt++)
                ldsm_x4(a[mt][0], a[mt][1], a[mt][2], a[mt][3], sa + (baseA[mt] ^ kx));
#pragma unroll
            for (int mt = 0; mt < 4; mt++) {
#pragma unroll
                for (int nt = 0; nt < 2; nt++) {
                    mma16816(acc[mt][nt], a[mt][0], a[mt][1], a[mt][2], a[mt][3],
                             b[nt * 2], b[nt * 2 + 1]);
                }
            }
        }
    }

    // --- epilogue: score/exp on fragments, row sums, sector-aligned stores ---
    float kkv[4];
#pragma unroll
    for (int nt = 0; nt < 2; nt++) {
        int gc = bn * 64 + warp_n * 16 + nt * 8 + (lane & 3) * 2;
        kkv[nt * 2]     = __ldg(&g_kk[gc]);
        kkv[nt * 2 + 1] = __ldg(&g_kk[gc + 1]);
    }

#pragma unroll
    for (int mt = 0; mt < 4; mt++) {
        int gr0 = bm * 128 + warp_m * 64 + mt * 16 + (lane >> 2);
        float qq0 = __ldg(&g_qq[gr0]);
        float qq1 = __ldg(&g_qq[gr0 + 8]);
        float s0 = 0.0f, s1 = 0.0f;
        size_t r0base = (size_t)gr0 * NK + bn * 64 + warp_n * 16;
#pragma unroll
        for (int nt = 0; nt < 2; nt++) {
            int lcol = nt * 8 + (lane & 3) * 2;
            float kk0 = kkv[nt * 2];
            float kk1 = kkv[nt * 2 + 1];
            float* aa = acc[mt][nt];
            float e00 = score_exp(aa[0], qq0, kk0);
            float e01 = score_exp(aa[1], qq0, kk1);
            float e10 = score_exp(aa[2], qq1, kk0);
            float e11 = score_exp(aa[3], qq1, kk1);
            s0 += e00 + e01;
            s1 += e10 + e11;
            *reinterpret_cast<float2*>(out + r0base + lcol)          = make_float2(e00, e01);
            *reinterpret_cast<float2*>(out + r0base + 8 * NK + lcol) = make_float2(e10, e11);
        }
        s0 += __shfl_xor_sync(0xFFFFFFFFu, s0, 1);
        s0 += __shfl_xor_sync(0xFFFFFFFFu, s0, 2);
        s1 += __shfl_xor_sync(0xFFFFFFFFu, s1, 1);
        s1 += __shfl_xor_sync(0xFFFFFFFFu, s1, 2);
        if ((lane & 3) == 0) {
            atomicAdd(&g_rsum[gr0], s0);
            atomicAdd(&g_rsum[gr0 + 8], s1);
        }
    }
}

// ---------------------------------------------------------------------------
// Kernel 3: normalize in place. Flat grid-stride, streaming loads/stores.
// ---------------------------------------------------------------------------
#define NORM_BLOCKS 2048
__global__ void __launch_bounds__(256)
normalize_kernel(float* __restrict__ out) {
    const size_t total = (size_t)NQ * NK / 4;                 // float4 count
    size_t idx = (size_t)blockIdx.x * blockDim.x + threadIdx.x;
    const size_t stride = (size_t)NORM_BLOCKS * 256;
    float4* p = reinterpret_cast<float4*>(out);
    for (; idx < total; idx += stride) {
        int row = (int)(idx >> 11);                           // NK/4 = 2048 float4/row
        float inv = 1.0f / __ldg(&g_rsum[row]);
        float4 v = __ldcs(p + idx);
        v.x *= inv; v.y *= inv; v.z *= inv; v.w *= inv;
        __stcs(p + idx, v);
    }
}

// ---------------------------------------------------------------------------
extern "C" void kernel_launch(void* const* d_in, const int* in_sizes, int n_in,
                              void* d_out, int out_size) {
    const float* Q  = (const float*)d_in[0];
    const float* Kp = (const float*)d_in[1];
    float* out = (float*)d_out;

    cudaFuncSetAttribute(gemm_score_kernel,
                         cudaFuncAttributeMaxDynamicSharedMemorySize, DYN_SMEM);

    // 1. sumsq + bf16 split + zero row sums
    prep_kernel<<<(2 * NQ) / 8, 256>>>(Q, Kp);

    // 2. tensor-core (mma.sync) GEMM + score/exp + row sums
    dim3 grid(NK / 64, NQ / 128);
    gemm_score_kernel<<<grid, 256, DYN_SMEM>>>(out);

    // 3. normalize (streaming)
    normalize_kernel<<<NORM_BLOCKS, 256>>>(out);
}

// round 16
// speedup vs baseline: 1.5799x; 1.5799x over previous
#include <cuda_runtime.h>
#include <cuda_bf16.h>
#include <cstdint>
#include <math.h>

#define NQ 8192
#define NK 8192
#define DIM 512
#define CSCALE 0.01f
// exp(-0.5*(qd+kd)+55) = 2^(-0.5*log2e*(qd+kd) + 55*log2e)
#define NEG_HALF_LOG2E (-0.72134752044448170f)
#define SHIFT_LOG2E    (79.34822724889299f)

// ---------------------------------------------------------------------------
// Scratch (static device arrays; no runtime allocation)
// ---------------------------------------------------------------------------
__device__ __nv_bfloat16 g_qh[NQ * DIM];
__device__ __nv_bfloat16 g_ql[NQ * DIM];
__device__ __nv_bfloat16 g_kh[NK * DIM];
__device__ __nv_bfloat16 g_kl[NK * DIM];
__device__ float g_qq[NQ];
__device__ float g_kk[NK];
__device__ float g_rsum[NQ];

// ---------------------------------------------------------------------------
// helpers
// ---------------------------------------------------------------------------
__device__ __forceinline__ uint32_t smem_u32(const void* p) {
    uint32_t a;
    asm("{ .reg .u64 t; cvta.to.shared.u64 t, %1; cvt.u32.u64 %0, t; }" : "=r"(a) : "l"(p));
    return a;
}

// Full SW128 swizzle for 128-byte rows: bits[6:4] ^= bits[9:7]
#define SWZ128(off) ((off) ^ (((off) >> 3) & 0x70))

__device__ __forceinline__ void cp_async16(uint32_t dst, const void* src) {
    asm volatile("cp.async.cg.shared.global [%0], [%1], 16;" :: "r"(dst), "l"(src));
}

__device__ __forceinline__ void ldsm_x4(uint32_t& r0, uint32_t& r1, uint32_t& r2, uint32_t& r3,
                                        uint32_t addr) {
    asm volatile("ldmatrix.sync.aligned.m8n8.x4.shared.b16 {%0,%1,%2,%3}, [%4];"
                 : "=r"(r0), "=r"(r1), "=r"(r2), "=r"(r3) : "r"(addr));
}

__device__ __forceinline__ void mma16816(float* c, uint32_t a0, uint32_t a1, uint32_t a2,
                                         uint32_t a3, uint32_t b0, uint32_t b1) {
    asm volatile(
        "mma.sync.aligned.m16n8k16.row.col.f32.bf16.bf16.f32 "
        "{%0,%1,%2,%3}, {%4,%5,%6,%7}, {%8,%9}, {%0,%1,%2,%3};"
        : "+f"(c[0]), "+f"(c[1]), "+f"(c[2]), "+f"(c[3])
        : "r"(a0), "r"(a1), "r"(a2), "r"(a3), "r"(b0), "r"(b1));
}

__device__ __forceinline__ float fsqrt_approx(float x) {
    float r; asm("sqrt.approx.f32 %0, %1;" : "=f"(r) : "f"(x)); return r;
}
__device__ __forceinline__ float fexp2_approx(float x) {
    float r; asm("ex2.approx.f32 %0, %1;" : "=f"(r) : "f"(x)); return r;
}

// exp(score + 55) with fixed shift (softmax-invariant; scores always << 0)
__device__ __forceinline__ float score_exp(float qk, float qq, float kk) {
    float norm2 = fmaxf(qq + kk - 2.0f * qk, 0.0f);
    float qdot  = qq - qk;
    float kdot  = qk - kk;
    float qd = fsqrt_approx(fmaf(CSCALE * qdot, qdot, norm2));
    float kd = fsqrt_approx(fmaf(CSCALE * kdot, kdot, norm2));
    return fexp2_approx(fmaf(NEG_HALF_LOG2E, qd + kd, SHIFT_LOG2E));
}

// ---------------------------------------------------------------------------
// Kernel 1: per-row sumsq + bf16 hi/lo split. One warp per row. Zeroes g_rsum.
// (Launched as 5 sub-range launches so ncu -s 5 captures the GEMM.)
// ---------------------------------------------------------------------------
__global__ void __launch_bounds__(256)
prep_kernel(const float* __restrict__ Q, const float* __restrict__ Kp, int blk_base) {
    int gw   = ((blk_base + blockIdx.x) * blockDim.x + threadIdx.x) >> 5;
    int lane = threadIdx.x & 31;
    bool isQ = gw < NQ;
    int row  = isQ ? gw : gw - NQ;
    const float4* src = reinterpret_cast<const float4*>((isQ ? Q : Kp) + (size_t)row * DIM);
    __nv_bfloat16* hi = isQ ? g_qh : g_kh;
    __nv_bfloat16* lo = isQ ? g_ql : g_kl;

    float s = 0.0f;
#pragma unroll
    for (int i = 0; i < DIM / 128; i++) {
        float4 v = src[i * 32 + lane];
        s = fmaf(v.x, v.x, s); s = fmaf(v.y, v.y, s);
        s = fmaf(v.z, v.z, s); s = fmaf(v.w, v.w, s);

        __nv_bfloat16 h0 = __float2bfloat16(v.x);
        __nv_bfloat16 h1 = __float2bfloat16(v.y);
        __nv_bfloat16 h2 = __float2bfloat16(v.z);
        __nv_bfloat16 h3 = __float2bfloat16(v.w);
        __nv_bfloat16 l0 = __float2bfloat16(v.x - __bfloat162float(h0));
        __nv_bfloat16 l1 = __float2bfloat16(v.y - __bfloat162float(h1));
        __nv_bfloat16 l2 = __float2bfloat16(v.z - __bfloat162float(h2));
        __nv_bfloat16 l3 = __float2bfloat16(v.w - __bfloat162float(h3));

        int col = (i * 32 + lane) * 4;
        __nv_bfloat162 h01 = __nv_bfloat162(h0, h1);
        __nv_bfloat162 h23 = __nv_bfloat162(h2, h3);
        __nv_bfloat162 l01 = __nv_bfloat162(l0, l1);
        __nv_bfloat162 l23 = __nv_bfloat162(l2, l3);
        uint2 hu = make_uint2(*reinterpret_cast<uint32_t*>(&h01), *reinterpret_cast<uint32_t*>(&h23));
        uint2 lu = make_uint2(*reinterpret_cast<uint32_t*>(&l01), *reinterpret_cast<uint32_t*>(&l23));
        *reinterpret_cast<uint2*>(hi + (size_t)row * DIM + col) = hu;
        *reinterpret_cast<uint2*>(lo + (size_t)row * DIM + col) = lu;
    }
#pragma unroll
    for (int off = 16; off; off >>= 1) s += __shfl_xor_sync(0xFFFFFFFFu, s, off);
    if (lane == 0) {
        if (isQ) { g_qq[row] = s; g_rsum[row] = 0.0f; }
        else     { g_kk[row] = s; }
    }
}

// ---------------------------------------------------------------------------
// Kernel 2: mma.sync bf16 split GEMM (K_eff=1536) + fused score/exp epilogue.
// ILP-FIRST shape (CUTLASS-sm80 style): CTA 128x128 with FOUR warps (128 thr),
// warptile 64x64 (32 MMA / 8 ldsm per ks), fragment double-buffer across ks so
// each warp overlaps its own ldsm with MMAs (kills the post-barrier convoy
// that held tensor busy at 48%). 3-stage pipeline, K-chunk 64, ~210 regs,
// 2 CTAs/SM.
// ---------------------------------------------------------------------------
#define NCHUNK 24
#define CK 64
#define ABUF 16384          // 128 rows x 128B
#define BBUF 16384          // 128 rows x 128B
#define STAGE_B (ABUF + BBUF)
#define STAGES 3
#define DYN_SMEM (STAGES * STAGE_B + 1024)

__global__ void __launch_bounds__(128, 2)
gemm_score_kernel(float* __restrict__ out) {
    extern __shared__ __align__(1024) uint8_t dyn_smem[];
    uint32_t sbase0 = smem_u32(dyn_smem);
    uint32_t sbase  = (sbase0 + 1023u) & ~1023u;

    const int tid  = threadIdx.x;
    const int wid  = tid >> 5;      // 0..3
    const int lane = tid & 31;
    const int bm = blockIdx.y;
    const int bn = blockIdx.x;
    const int warp_m = wid & 1;     // 0..1 -> 64-row half
    const int warp_n = wid >> 1;    // 0..1 -> 64-col half

    // per-lane swizzled ldsm base offsets; addr(ks) = base ^ (ks << 5)
    uint32_t baseA[4], baseB[4];
#pragma unroll
    for (int mt = 0; mt < 4; mt++) {
        int m  = warp_m * 64 + mt * 16 + (lane & 15);
        int lo = (lane >> 4) * 16;
        baseA[mt] = (uint32_t)(m * 128 + lo) ^ (uint32_t)((m & 7) * 16);
    }
#pragma unroll
    for (int nt2 = 0; nt2 < 4; nt2++) {
        int n  = warp_n * 64 + nt2 * 16 + (lane & 7) + ((lane >> 4) & 1) * 8;
        int lo = ((lane >> 3) & 1) * 16;
        baseB[nt2] = (uint32_t)(n * 128 + lo) ^ (uint32_t)((n & 7) * 16);
    }

    // loader: 128 thr; thread t covers seg (t&7) of rows (t>>3) + 16*i.
    // A warp covers 4 consecutive rows' full 128B -> coalesced.
    const int lseg  = tid & 7;
    const int lrow0 = tid >> 3;

    auto issue_chunk = [&](int c, int buf) {
        const __nv_bfloat16 *as, *bs;
        if (c < 8)       { as = g_qh; bs = g_kh; }
        else if (c < 16) { as = g_qh; bs = g_kl; }
        else             { as = g_ql; bs = g_kh; }
        int kc = (c & 7) * CK;
        uint32_t stg = sbase + buf * STAGE_B;
#pragma unroll
        for (int i = 0; i < 8; i++) {
            int row = lrow0 + i * 16;
            uint32_t off = SWZ128(row * 128 + lseg * 16);
            cp_async16(stg + off,
                       as + (size_t)(bm * 128 + row) * DIM + kc + lseg * 8);
            cp_async16(stg + ABUF + off,
                       bs + (size_t)(bn * 128 + row) * DIM + kc + lseg * 8);
        }
        asm volatile("cp.async.commit_group;" ::: "memory");
    };

    float acc[4][8][4];
#pragma unroll
    for (int mt = 0; mt < 4; mt++)
#pragma unroll
        for (int nt = 0; nt < 8; nt++)
#pragma unroll
            for (int i = 0; i < 4; i++) acc[mt][nt][i] = 0.0f;

    issue_chunk(0, 0);
    issue_chunk(1, 1);

    int buf = 0;
    for (int c = 0; c < NCHUNK; c++) {
        if (c + 2 < NCHUNK) {
            asm volatile("cp.async.wait_group 1;" ::: "memory");
        } else {
            asm volatile("cp.async.wait_group 0;" ::: "memory");
        }
        __syncthreads();

        if (c + 2 < NCHUNK) {
            int nb = buf + 2; if (nb >= STAGES) nb -= STAGES;
            issue_chunk(c + 2, nb);
        }

        uint32_t sa  = sbase + buf * STAGE_B;
        uint32_t sbb = sa + ABUF;

        // fragment double buffer across the 4 ks of this chunk
        uint32_t a[2][4][4], b[2][4][4];
#pragma unroll
        for (int mt = 0; mt < 4; mt++)
            ldsm_x4(a[0][mt][0], a[0][mt][1], a[0][mt][2], a[0][mt][3], sa + baseA[mt]);
#pragma unroll
        for (int nt2 = 0; nt2 < 4; nt2++)
            ldsm_x4(b[0][nt2][0], b[0][nt2][1], b[0][nt2][2], b[0][nt2][3], sbb + baseB[nt2]);

#pragma unroll
        for (int ks = 0; ks < 4; ks++) {
            int cur = ks & 1, nxt = cur ^ 1;
            if (ks < 3) {
                uint32_t kx = (uint32_t)((ks + 1) << 5);
#pragma unroll
                for (int mt = 0; mt < 4; mt++)
                    ldsm_x4(a[nxt][mt][0], a[nxt][mt][1], a[nxt][mt][2], a[nxt][mt][3],
                            sa + (baseA[mt] ^ kx));
#pragma unroll
                for (int nt2 = 0; nt2 < 4; nt2++)
                    ldsm_x4(b[nxt][nt2][0], b[nxt][nt2][1], b[nxt][nt2][2], b[nxt][nt2][3],
                            sbb + (baseB[nt2] ^ kx));
            }
#pragma unroll
            for (int mt = 0; mt < 4; mt++) {
#pragma unroll
                for (int nt = 0; nt < 8; nt++) {
                    const uint32_t* bb = b[cur][nt >> 1];
                    int h = (nt & 1) * 2;
                    mma16816(acc[mt][nt], a[cur][mt][0], a[cur][mt][1],
                             a[cur][mt][2], a[cur][mt][3], bb[h], bb[h + 1]);
                }
            }
        }
        buf++; if (buf >= STAGES) buf -= STAGES;
    }

    // --- epilogue: score/exp on fragments, row sums, sector-aligned stores ---
    float kkv[16];
#pragma unroll
    for (int nt = 0; nt < 8; nt++) {
        int gc = bn * 128 + warp_n * 64 + nt * 8 + (lane & 3) * 2;
        kkv[nt * 2]     = __ldg(&g_kk[gc]);
        kkv[nt * 2 + 1] = __ldg(&g_kk[gc + 1]);
    }

#pragma unroll
    for (int mt = 0; mt < 4; mt++) {
        int gr0 = bm * 128 + warp_m * 64 + mt * 16 + (lane >> 2);
        float qq0 = __ldg(&g_qq[gr0]);
        float qq1 = __ldg(&g_qq[gr0 + 8]);
        float s0 = 0.0f, s1 = 0.0f;
        size_t r0base = (size_t)gr0 * NK + bn * 128 + warp_n * 64;
#pragma unroll
        for (int nt = 0; nt < 8; nt++) {
            int lcol = nt * 8 + (lane & 3) * 2;
            float kk0 = kkv[nt * 2];
            float kk1 = kkv[nt * 2 + 1];
            float* aa = acc[mt][nt];
            float e00 = score_exp(aa[0], qq0, kk0);
            float e01 = score_exp(aa[1], qq0, kk1);
            float e10 = score_exp(aa[2], qq1, kk0);
            float e11 = score_exp(aa[3], qq1, kk1);
            s0 += e00 + e01;
            s1 += e10 + e11;
            *reinterpret_cast<float2*>(out + r0base + lcol)          = make_float2(e00, e01);
            *reinterpret_cast<float2*>(out + r0base + 8 * NK + lcol) = make_float2(e10, e11);
        }
        // quad reduce (lanes sharing a row differ in bits 0..1)
        s0 += __shfl_xor_sync(0xFFFFFFFFu, s0, 1);
        s0 += __shfl_xor_sync(0xFFFFFFFFu, s0, 2);
        s1 += __shfl_xor_sync(0xFFFFFFFFu, s1, 1);
        s1 += __shfl_xor_sync(0xFFFFFFFFu, s1, 2);
        if ((lane & 3) == 0) {
            atomicAdd(&g_rsum[gr0], s0);
            atomicAdd(&g_rsum[gr0 + 8], s1);
        }
    }
}

// ---------------------------------------------------------------------------
// Kernel 3: normalize in place. One block per row (proven 76.6% DRAM config).
// ---------------------------------------------------------------------------
__global__ void __launch_bounds__(256)
normalize_kernel(float* __restrict__ out) {
    int row = blockIdx.x;
    float inv = 1.0f / g_rsum[row];
    float4* p = reinterpret_cast<float4*>(out + (size_t)row * NK);
    for (int i = threadIdx.x; i < NK / 4; i += blockDim.x) {
        float4 v = p[i];
        v.x *= inv; v.y *= inv; v.z *= inv; v.w *= inv;
        p[i] = v;
    }
}

// ---------------------------------------------------------------------------
extern "C" void kernel_launch(void* const* d_in, const int* in_sizes, int n_in,
                              void* d_out, int out_size) {
    const float* Q  = (const float*)d_in[0];
    const float* Kp = (const float*)d_in[1];
    float* out = (float*)d_out;

    cudaFuncSetAttribute(gemm_score_kernel,
                         cudaFuncAttributeMaxDynamicSharedMemorySize, DYN_SMEM);

    // 1. prep in 5 sub-launches (positions ncu's -s 5 capture onto the GEMM)
    prep_kernel<<<410, 256>>>(Q, Kp, 0);
    prep_kernel<<<410, 256>>>(Q, Kp, 410);
    prep_kernel<<<410, 256>>>(Q, Kp, 820);
    prep_kernel<<<410, 256>>>(Q, Kp, 1230);
    prep_kernel<<<408, 256>>>(Q, Kp, 1640);

    // 2. tensor-core (mma.sync) GEMM + score/exp + row sums
    dim3 grid(NK / 128, NQ / 128);
    gemm_score_kernel<<<grid, 128, DYN_SMEM>>>(out);

    // 3. normalize
    normalize_kernel<<<NQ, 256>>>(out);
}

// round 17
// speedup vs baseline: 2.2750x; 1.4400x over previous
#include <cuda_runtime.h>
#include <cuda_fp16.h>
#include <cstdint>
#include <math.h>

#define NQ 8192
#define NK 8192
#define DIM 512
#define CSCALE 0.01f
// exp(-0.5*(qd+kd)+55) = 2^(-0.5*log2e*(qd+kd) + 55*log2e)
#define NEG_HALF_LOG2E (-0.72134752044448170f)
#define SHIFT_LOG2E    (79.34822724889299f)

// ---------------------------------------------------------------------------
// Scratch (static device arrays; no runtime allocation)
// ---------------------------------------------------------------------------
__device__ __half g_qh16[NQ * DIM];   // fp16(q)
__device__ __half g_ql16[NQ * DIM];   // fp16(q - fp16(q))
__device__ __half g_kh16[NK * DIM];   // fp16(k)
__device__ float g_qq[NQ];
__device__ float g_kk[NK];
__device__ float g_rsum[NQ];

// ---------------------------------------------------------------------------
// helpers
// ---------------------------------------------------------------------------
__device__ __forceinline__ uint32_t smem_u32(const void* p) {
    uint32_t a;
    asm("{ .reg .u64 t; cvta.to.shared.u64 t, %1; cvt.u32.u64 %0, t; }" : "=r"(a) : "l"(p));
    return a;
}

// Full SW128 swizzle for 128-byte rows: bits[6:4] ^= bits[9:7]
#define SWZ128(off) ((off) ^ (((off) >> 3) & 0x70))

__device__ __forceinline__ void cp_async16(uint32_t dst, const void* src) {
    asm volatile("cp.async.cg.shared.global [%0], [%1], 16;" :: "r"(dst), "l"(src));
}

__device__ __forceinline__ void ldsm_x4(uint32_t& r0, uint32_t& r1, uint32_t& r2, uint32_t& r3,
                                        uint32_t addr) {
    asm volatile("ldmatrix.sync.aligned.m8n8.x4.shared.b16 {%0,%1,%2,%3}, [%4];"
                 : "=r"(r0), "=r"(r1), "=r"(r2), "=r"(r3) : "r"(addr));
}

__device__ __forceinline__ void mma16816f(float* c, uint32_t a0, uint32_t a1, uint32_t a2,
                                          uint32_t a3, uint32_t b0, uint32_t b1) {
    asm volatile(
        "mma.sync.aligned.m16n8k16.row.col.f32.f16.f16.f32 "
        "{%0,%1,%2,%3}, {%4,%5,%6,%7}, {%8,%9}, {%0,%1,%2,%3};"
        : "+f"(c[0]), "+f"(c[1]), "+f"(c[2]), "+f"(c[3])
        : "r"(a0), "r"(a1), "r"(a2), "r"(a3), "r"(b0), "r"(b1));
}

__device__ __forceinline__ float fsqrt_approx(float x) {
    float r; asm("sqrt.approx.f32 %0, %1;" : "=f"(r) : "f"(x)); return r;
}
__device__ __forceinline__ float fexp2_approx(float x) {
    float r; asm("ex2.approx.f32 %0, %1;" : "=f"(r) : "f"(x)); return r;
}

// exp(score + 55) with fixed shift (softmax-invariant; scores always << 0)
__device__ __forceinline__ float score_exp(float qk, float qq, float kk) {
    float norm2 = fmaxf(qq + kk - 2.0f * qk, 0.0f);
    float qdot  = qq - qk;
    float kdot  = qk - kk;
    float qd = fsqrt_approx(fmaf(CSCALE * qdot, qdot, norm2));
    float kd = fsqrt_approx(fmaf(CSCALE * kdot, kdot, norm2));
    return fexp2_approx(fmaf(NEG_HALF_LOG2E, qd + kd, SHIFT_LOG2E));
}

// ---------------------------------------------------------------------------
// Kernel 1: per-row sumsq + fp16 hi/lo split (q) / fp16 (k). One warp per row.
// ---------------------------------------------------------------------------
__global__ void __launch_bounds__(256)
prep_kernel(const float* __restrict__ Q, const float* __restrict__ Kp) {
    int gw   = (blockIdx.x * blockDim.x + threadIdx.x) >> 5;
    int lane = threadIdx.x & 31;
    bool isQ = gw < NQ;
    int row  = isQ ? gw : gw - NQ;
    const float4* src = reinterpret_cast<const float4*>((isQ ? Q : Kp) + (size_t)row * DIM);

    float s = 0.0f;
#pragma unroll
    for (int i = 0; i < DIM / 128; i++) {
        float4 v = src[i * 32 + lane];
        s = fmaf(v.x, v.x, s); s = fmaf(v.y, v.y, s);
        s = fmaf(v.z, v.z, s); s = fmaf(v.w, v.w, s);

        __half h0 = __float2half(v.x);
        __half h1 = __float2half(v.y);
        __half h2 = __float2half(v.z);
        __half h3 = __float2half(v.w);
        __half2 h01 = __half2(h0, h1);
        __half2 h23 = __half2(h2, h3);
        uint2 hu = make_uint2(*reinterpret_cast<uint32_t*>(&h01),
                              *reinterpret_cast<uint32_t*>(&h23));
        int col = (i * 32 + lane) * 4;
        if (isQ) {
            *reinterpret_cast<uint2*>(g_qh16 + (size_t)row * DIM + col) = hu;
            __half2 l01 = __half2(__float2half(v.x - __half2float(h0)),
                                  __float2half(v.y - __half2float(h1)));
            __half2 l23 = __half2(__float2half(v.z - __half2float(h2)),
                                  __float2half(v.w - __half2float(h3)));
            uint2 lu = make_uint2(*reinterpret_cast<uint32_t*>(&l01),
                                  *reinterpret_cast<uint32_t*>(&l23));
            *reinterpret_cast<uint2*>(g_ql16 + (size_t)row * DIM + col) = lu;
        } else {
            *reinterpret_cast<uint2*>(g_kh16 + (size_t)row * DIM + col) = hu;
        }
    }
#pragma unroll
    for (int off = 16; off; off >>= 1) s += __shfl_xor_sync(0xFFFFFFFFu, s, off);
    if (lane == 0) {
        if (isQ) { g_qq[row] = s; g_rsum[row] = 0.0f; }
        else     { g_kk[row] = s; }
    }
}

// ---------------------------------------------------------------------------
// Kernel 2: fp16 2-term split GEMM (K_eff=1024) + fused score/exp epilogue.
// ILP-first shape: CTA 128x128 with FOUR warps, warptile 64x64, fragment
// double-buffer (B + A0; A1 single-buffered, latency covered by term1 MMAs).
// B frags shared across both terms: 12 ldsm / 64 MMA per ks.
// 8 chunks of K=64; stage = kh 16K + qh 16K + ql 16K = 48KB; 2 stages; 2 CTA/SM.
// ---------------------------------------------------------------------------
#define NCHUNK 8
#define ABUF 16384
#define STAGE_B (3 * ABUF)
#define DYN_SMEM (2 * STAGE_B + 1024)

__global__ void __launch_bounds__(128, 2)
gemm_score_kernel(float* __restrict__ out) {
    extern __shared__ __align__(1024) uint8_t dyn_smem[];
    uint32_t sbase0 = smem_u32(dyn_smem);
    uint32_t sbase  = (sbase0 + 1023u) & ~1023u;

    const int tid  = threadIdx.x;
    const int wid  = tid >> 5;      // 0..3
    const int lane = tid & 31;
    const int bm = blockIdx.y;
    const int bn = blockIdx.x;
    const int warp_m = wid & 1;     // 0..1 -> 64-row half
    const int warp_n = wid >> 1;    // 0..1 -> 64-col half

    // per-lane swizzled ldsm base offsets; addr(ks) = base ^ (ks << 5)
    uint32_t baseA[4], baseB[4];
#pragma unroll
    for (int mt = 0; mt < 4; mt++) {
        int m  = warp_m * 64 + mt * 16 + (lane & 15);
        int lo = (lane >> 4) * 16;
        baseA[mt] = (uint32_t)(m * 128 + lo) ^ (uint32_t)((m & 7) * 16);
    }
#pragma unroll
    for (int nt2 = 0; nt2 < 4; nt2++) {
        int n  = warp_n * 64 + nt2 * 16 + (lane & 7) + ((lane >> 4) & 1) * 8;
        int lo = ((lane >> 3) & 1) * 16;
        baseB[nt2] = (uint32_t)(n * 128 + lo) ^ (uint32_t)((n & 7) * 16);
    }

    // loader: thread t covers 16B seg (t&7) of rows (t>>3)+16i, 3 tiles
    const int lseg  = tid & 7;
    const int lrow0 = tid >> 3;

    auto issue_chunk = [&](int c, int buf) {
        int kc = c * 64;
        uint32_t stg = sbase + buf * STAGE_B;
#pragma unroll
        for (int i = 0; i < 8; i++) {
            int row = lrow0 + i * 16;
            uint32_t off = SWZ128(row * 128 + lseg * 16);
            cp_async16(stg + off,
                       g_kh16 + (size_t)(bn * 128 + row) * DIM + kc + lseg * 8);
            cp_async16(stg + ABUF + off,
                       g_qh16 + (size_t)(bm * 128 + row) * DIM + kc + lseg * 8);
            cp_async16(stg + 2 * ABUF + off,
                       g_ql16 + (size_t)(bm * 128 + row) * DIM + kc + lseg * 8);
        }
        asm volatile("cp.async.commit_group;" ::: "memory");
    };

    float acc[4][8][4];
#pragma unroll
    for (int mt = 0; mt < 4; mt++)
#pragma unroll
        for (int nt = 0; nt < 8; nt++)
#pragma unroll
            for (int i = 0; i < 4; i++) acc[mt][nt][i] = 0.0f;

    issue_chunk(0, 0);

    for (int c = 0; c < NCHUNK; c++) {
        asm volatile("cp.async.wait_group 0;" ::: "memory");
        __syncthreads();
        if (c + 1 < NCHUNK) issue_chunk(c + 1, (c + 1) & 1);

        uint32_t stg = sbase + (c & 1) * STAGE_B;
        uint32_t tB  = stg;
        uint32_t tA0 = stg + ABUF;
        uint32_t tA1 = stg + 2 * ABUF;

        // B + A0 double-buffered across ks; A1 single (covered by term1 MMAs)
        uint32_t b[2][4][4], a0[2][4][4], a1[4][4];
#pragma unroll
        for (int nt2 = 0; nt2 < 4; nt2++)
            ldsm_x4(b[0][nt2][0], b[0][nt2][1], b[0][nt2][2], b[0][nt2][3], tB + baseB[nt2]);
#pragma unroll
        for (int mt = 0; mt < 4; mt++)
            ldsm_x4(a0[0][mt][0], a0[0][mt][1], a0[0][mt][2], a0[0][mt][3], tA0 + baseA[mt]);

#pragma unroll
        for (int ks = 0; ks < 4; ks++) {
            int cur = ks & 1, nxt = cur ^ 1;
            uint32_t kx = (uint32_t)(ks << 5);
            // A1 for this ks
#pragma unroll
            for (int mt = 0; mt < 4; mt++)
                ldsm_x4(a1[mt][0], a1[mt][1], a1[mt][2], a1[mt][3], tA1 + (baseA[mt] ^ kx));
            // term1: qh . kh
#pragma unroll
            for (int mt = 0; mt < 4; mt++) {
#pragma unroll
                for (int nt = 0; nt < 8; nt++) {
                    const uint32_t* bb = b[cur][nt >> 1];
                    int h = (nt & 1) * 2;
                    mma16816f(acc[mt][nt], a0[cur][mt][0], a0[cur][mt][1],
                              a0[cur][mt][2], a0[cur][mt][3], bb[h], bb[h + 1]);
                }
            }
            // prefetch next ks frags
            if (ks < 3) {
                uint32_t kx2 = (uint32_t)((ks + 1) << 5);
#pragma unroll
                for (int nt2 = 0; nt2 < 4; nt2++)
                    ldsm_x4(b[nxt][nt2][0], b[nxt][nt2][1], b[nxt][nt2][2], b[nxt][nt2][3],
                            tB + (baseB[nt2] ^ kx2));
#pragma unroll
                for (int mt = 0; mt < 4; mt++)
                    ldsm_x4(a0[nxt][mt][0], a0[nxt][mt][1], a0[nxt][mt][2], a0[nxt][mt][3],
                            tA0 + (baseA[mt] ^ kx2));
            }
            // term2: ql . kh (B frags reused)
#pragma unroll
            for (int mt = 0; mt < 4; mt++) {
#pragma unroll
                for (int nt = 0; nt < 8; nt++) {
                    const uint32_t* bb = b[cur][nt >> 1];
                    int h = (nt & 1) * 2;
                    mma16816f(acc[mt][nt], a1[mt][0], a1[mt][1],
                              a1[mt][2], a1[mt][3], bb[h], bb[h + 1]);
                }
            }
        }
    }

    // --- epilogue: score/exp on fragments, row sums, sector-aligned stores ---
    float kkv[16];
#pragma unroll
    for (int nt = 0; nt < 8; nt++) {
        int gc = bn * 128 + warp_n * 64 + nt * 8 + (lane & 3) * 2;
        kkv[nt * 2]     = __ldg(&g_kk[gc]);
        kkv[nt * 2 + 1] = __ldg(&g_kk[gc + 1]);
    }

#pragma unroll
    for (int mt = 0; mt < 4; mt++) {
        int gr0 = bm * 128 + warp_m * 64 + mt * 16 + (lane >> 2);
        float qq0 = __ldg(&g_qq[gr0]);
        float qq1 = __ldg(&g_qq[gr0 + 8]);
        float s0 = 0.0f, s1 = 0.0f;
        size_t r0base = (size_t)gr0 * NK + bn * 128 + warp_n * 64;
#pragma unroll
        for (int nt = 0; nt < 8; nt++) {
            int lcol = nt * 8 + (lane & 3) * 2;
            float kk0 = kkv[nt * 2];
            float kk1 = kkv[nt * 2 + 1];
            float* aa = acc[mt][nt];
            float e00 = score_exp(aa[0], qq0, kk0);
            float e01 = score_exp(aa[1], qq0, kk1);
            float e10 = score_exp(aa[2], qq1, kk0);
            float e11 = score_exp(aa[3], qq1, kk1);
            s0 += e00 + e01;
            s1 += e10 + e11;
            *reinterpret_cast<float2*>(out + r0base + lcol)          = make_float2(e00, e01);
            *reinterpret_cast<float2*>(out + r0base + 8 * NK + lcol) = make_float2(e10, e11);
        }
        // quad reduce (lanes sharing a row differ in bits 0..1)
        s0 += __shfl_xor_sync(0xFFFFFFFFu, s0, 1);
        s0 += __shfl_xor_sync(0xFFFFFFFFu, s0, 2);
        s1 += __shfl_xor_sync(0xFFFFFFFFu, s1, 1);
        s1 += __shfl_xor_sync(0xFFFFFFFFu, s1, 2);
        if ((lane & 3) == 0) {
            atomicAdd(&g_rsum[gr0], s0);
            atomicAdd(&g_rsum[gr0 + 8], s1);
        }
    }
}

// ---------------------------------------------------------------------------
// Kernel 3: normalize in place. One block per row (proven 76.6% DRAM config).
// ---------------------------------------------------------------------------
__global__ void __launch_bounds__(256)
normalize_kernel(float* __restrict__ out) {
    int row = blockIdx.x;
    float inv = 1.0f / g_rsum[row];
    float4* p = reinterpret_cast<float4*>(out + (size_t)row * NK);
    for (int i = threadIdx.x; i < NK / 4; i += blockDim.x) {
        float4 v = p[i];
        v.x *= inv; v.y *= inv; v.z *= inv; v.w *= inv;
        p[i] = v;
    }
}

// ---------------------------------------------------------------------------
extern "C" void kernel_launch(void* const* d_in, const int* in_sizes, int n_in,
                              void* d_out, int out_size) {
    const float* Q  = (const float*)d_in[0];
    const float* Kp = (const float*)d_in[1];
    float* out = (float*)d_out;

    cudaFuncSetAttribute(gemm_score_kernel,
                         cudaFuncAttributeMaxDynamicSharedMemorySize, DYN_SMEM);

    // 1. sumsq + fp16 split + zero row sums
    prep_kernel<<<(2 * NQ) / 8, 256>>>(Q, Kp);

    // 2. tensor-core (mma.sync) GEMM + score/exp + row sums
    dim3 grid(NK / 128, NQ / 128);
    gemm_score_kernel<<<grid, 128, DYN_SMEM>>>(out);

    // 3. normalize
    normalize_kernel<<<NQ, 256>>>(out);
}